// round 10
// baseline (speedup 1.0000x reference)
#include <cuda_runtime.h>
#include <math.h>

#define SQ3    1.7320508075688772f
#define IS3    0.57735026918962576451
#define HI_CLIP (0.99990f * SQ3)

// One 128-byte L1/L2 line: 8 intervals x (b0,b1,b2,b3), ALL centered at x = 1.
// Written identically by every CTA (idempotent); gather touches exactly 1 line.
__device__ __align__(128) float4 g_coef[8];

// ---------------------------------------------------------------------------
// Hot-path eval: u = xc - 1 (no per-interval knot!), 3-level FSEL binary
// search -> byte offset -> single-line LDG -> Horner. Exact spline.
// ---------------------------------------------------------------------------
__device__ __forceinline__ float eval_spline(float xv,
                                             float r1, float r2, float r3, float r4,
                                             float r5, float r6, float r7)
{
    float xc = fminf(xv, HI_CLIP);            // inputs >= 0
    float u  = xc - 1.0f;                     // common center; parallel to tree
    bool  b2 = xc >= r4;
    float p1 = b2 ? r6 : r2;
    float q1 = b2 ? r5 : r1;                  // depends only on b2
    float q2 = b2 ? r7 : r3;
    bool  b1 = xc >= p1;
    float p0 = b1 ? q2 : q1;
    bool  b0 = xc >= p0;
    int off = (b2 ? 64 : 0) + (b1 ? 32 : 0) + (b0 ? 16 : 0);
    float4 cf = *(const float4*)((const char*)g_coef + off);
    return fmaf(fmaf(fmaf(cf.w, u, cf.z), u, cf.y), u, cf.x);
}

// ---------------------------------------------------------------------------
// Single fused persistent kernel. Prologue per CTA (~1us, overlapped): stage
// weights -> tiny MLP -> softmax/cumsum knots -> symbolic de Boor -> Taylor
// shift (double precision) to common center x=1 -> store coef line.
// Main loop: streaming float4, 2 per thread per iteration.
// ---------------------------------------------------------------------------
__global__ __launch_bounds__(256) void fused_spline_kernel(
        const float* __restrict__ x, float* __restrict__ y, int n,
        const float* __restrict__ a,
        const float* __restrict__ W1, const float* __restrict__ b1,
        const float* __restrict__ W2, const float* __restrict__ b2,
        const float* __restrict__ Ww, const float* __restrict__ bw,
        const float* __restrict__ Wk, const float* __restrict__ bk)
{
    __shared__ float sA[1], sW1[16], sB1[16], sW2[256], sB2[16];
    __shared__ float sWW[144], sBW[9], sWK[112], sBK[7];
    __shared__ float n1[16], n2[16], w9[9], kl7[7];
    __shared__ float t[14], c[10], knx[8];

    int tid = threadIdx.x;

    // ---- stage all 577 weight scalars (one parallel load round) ----
    if (tid == 0) sA[0] = a[0];
    if (tid < 16) { sW1[tid] = W1[tid]; sB1[tid] = b1[tid]; sB2[tid] = b2[tid]; }
    sW2[tid] = W2[tid];
    if (tid < 144) sWW[tid] = Ww[tid];
    if (tid < 112) sWK[tid] = Wk[tid];
    if (tid >= 128 && tid < 137) sBW[tid - 128] = bw[tid - 128];
    if (tid >= 160 && tid < 167) sBK[tid - 160] = bk[tid - 160];
    __syncthreads();

    // ---- layer 1 ----
    if (tid < 16) n1[tid] = sinf(sA[0] * sW1[tid] + sB1[tid]);
    __syncthreads();

    // ---- layer 2 ----
    if (tid < 16) {
        float s = sB2[tid];
        #pragma unroll
        for (int j = 0; j < 16; j++) s += n1[j] * sW2[j * 16 + tid];
        n2[tid] = sinf(s);
    }
    __syncthreads();

    // ---- heads (two warps in parallel) ----
    if (tid < 9) {
        float s = sBW[tid];
        #pragma unroll
        for (int j = 0; j < 16; j++) s += n2[j] * sWW[j * 9 + tid];
        w9[tid] = s;
    }
    if (tid >= 32 && tid < 39) {
        int m = tid - 32;
        float s = sBK[m];
        #pragma unroll
        for (int j = 0; j < 16; j++) s += n2[j] * sWK[j * 7 + m];
        kl7[m] = s;
    }
    __syncthreads();

    // ---- softmax + cumsum -> knots; padded knot vector & control points ----
    if (tid == 0) {
        float mx = kl7[0];
        #pragma unroll
        for (int m = 1; m < 7; m++) mx = fmaxf(mx, kl7[m]);
        float e[7], ssum = 0.f;
        #pragma unroll
        for (int m = 0; m < 7; m++) { e[m] = expf(kl7[m] - mx); ssum += e[m]; }
        float inv = 1.f / ssum;
        float kk[8]; kk[0] = 0.f;
        float cum = 0.f;
        #pragma unroll
        for (int m = 0; m < 7; m++) { cum += e[m] * inv; kk[m + 1] = cum; }

        t[0] = t[1] = t[2] = 0.f;
        #pragma unroll
        for (int m = 0; m < 8; m++) { t[3 + m] = kk[m]; knx[m] = kk[m] * SQ3; }
        t[11] = t[12] = t[13] = 1.f;
        c[0] = 0.f;
        #pragma unroll
        for (int m = 0; m < 9; m++) c[1 + m] = w9[m];
    }
    __syncthreads();

    // ---- symbolic de Boor per interval (threads 0..7, knot index k = 3..10) ----
    if (tid < 8) {
        int k = tid + 3;
        float tkn = t[k];
        float d[4][4];   // d[j][m]: coefficient of u^m (normalized space, u = xq - t[k])
        #pragma unroll
        for (int j = 0; j < 4; j++) {
            int ci = k + j - 3; if (ci > 9) ci = 9;   // JAX clip-mode gather
            d[j][0] = c[ci]; d[j][1] = d[j][2] = d[j][3] = 0.f;
        }
        #pragma unroll
        for (int r = 1; r <= 3; r++) {
            #pragma unroll
            for (int j = 3; j >= 1; j--) {
                if (j < r) continue;
                float lo = t[k + j - 3];
                float hi = t[k + j + 1 - r];
                float dt = hi - lo;
                float invd = (dt > 0.f) ? (1.f / dt) : 0.f;   // guard empty tail interval
                float a0 = (tkn - lo) * invd;                 // alpha(u) = a0 + invd*u
                float em1 = 0.f;
                float nd[4];
                #pragma unroll
                for (int m = 0; m < 4; m++) {
                    float ee = d[j][m] - d[j - 1][m];
                    nd[m] = d[j - 1][m] + a0 * ee + invd * em1;
                    em1 = ee;
                }
                #pragma unroll
                for (int m = 0; m < 4; m++) d[j][m] = nd[m];
            }
        }
        // x-space coefficients about the interval knot, then Taylor-shift to
        // common center x = 1 (double precision to avoid rounding).
        double a0 = (double)d[3][0];
        double a1 = (double)d[3][1] * IS3;
        double a2 = (double)d[3][2] * (IS3 * IS3);
        double a3 = (double)d[3][3] * (IS3 * IS3 * IS3);
        double s  = 1.0 - (double)tkn * (double)SQ3;   // center - left_knot_x
        double b3d = a3;
        double b2d = a2 + 3.0 * a3 * s;
        double b1d = a1 + (2.0 * a2 + 3.0 * a3 * s) * s;
        double b0d = a0 + ((a3 * s + a2) * s + a1) * s;
        // Every CTA stores IDENTICAL bytes: cross-CTA races are benign.
        g_coef[tid] = make_float4((float)b0d, (float)b1d, (float)b2d, (float)b3d);
    }
    __threadfence_block();    // own-CTA visibility of the global coef line
    __syncthreads();

    // interior knots (x-space) in registers for the binary search
    const float r1 = knx[1], r2 = knx[2], r3 = knx[3], r4 = knx[4];
    const float r5 = knx[5], r6 = knx[6], r7 = knx[7];

    // ---- main streaming loop: 2 float4 per thread per iteration ----
    int n4 = n >> 2;
    const float4* __restrict__ xin  = (const float4*)x;
    float4* __restrict__       yout = (float4*)y;
    int step = gridDim.x * 512;

    for (int base = blockIdx.x * 512 + tid; base < n4; base += step) {
        int i1 = base + 256;
        bool p1 = i1 < n4;
        float4 v0 = __ldcg(xin + base);   // L2-resident stream; keep L1 for coef line
        float4 v1;
        if (p1) v1 = __ldcg(xin + i1);

        float4 o0;
        o0.x = eval_spline(v0.x, r1,r2,r3,r4,r5,r6,r7);
        o0.y = eval_spline(v0.y, r1,r2,r3,r4,r5,r6,r7);
        o0.z = eval_spline(v0.z, r1,r2,r3,r4,r5,r6,r7);
        o0.w = eval_spline(v0.w, r1,r2,r3,r4,r5,r6,r7);
        __stcs(yout + base, o0);          // streaming store: don't thrash L2

        if (p1) {
            float4 o1;
            o1.x = eval_spline(v1.x, r1,r2,r3,r4,r5,r6,r7);
            o1.y = eval_spline(v1.y, r1,r2,r3,r4,r5,r6,r7);
            o1.z = eval_spline(v1.z, r1,r2,r3,r4,r5,r6,r7);
            o1.w = eval_spline(v1.w, r1,r2,r3,r4,r5,r6,r7);
            __stcs(yout + i1, o1);
        }
    }

    // ---- scalar tail (n % 4), handled by block 0 ----
    int rem = n - (n4 << 2);
    if (rem > 0 && blockIdx.x == 0 && tid < rem) {
        int i = (n4 << 2) + tid;
        y[i] = eval_spline(x[i], r1,r2,r3,r4,r5,r6,r7);
    }
}

extern "C" void kernel_launch(void* const* d_in, const int* in_sizes, int n_in,
                              void* d_out, int out_size)
{
    const float* x  = (const float*)d_in[0];
    const float* a  = (const float*)d_in[1];
    const float* W1 = (const float*)d_in[2];
    const float* b1 = (const float*)d_in[3];
    const float* W2 = (const float*)d_in[4];
    const float* b2 = (const float*)d_in[5];
    const float* Ww = (const float*)d_in[6];
    const float* bw = (const float*)d_in[7];
    const float* Wk = (const float*)d_in[8];
    const float* bk = (const float*)d_in[9];
    float* out = (float*)d_out;

    int n  = out_size;
    int n4 = n >> 2;
    int blocks = 148 * 8;                      // persistent, ~1 wave
    int needed = (n4 + 511) / 512;
    if (needed < 1) needed = 1;
    if (blocks > needed) blocks = needed;

    fused_spline_kernel<<<blocks, 256>>>(x, out, n,
                                         a, W1, b1, W2, b2, Ww, bw, Wk, bk);
}

// round 13
// speedup vs baseline: 1.1528x; 1.1528x over previous
#include <cuda_runtime.h>
#include <math.h>

#define SQ3    1.7320508075688772f
#define IS3    0.57735026918962576451f
#define HI_CLIP (0.99990f * SQ3)

// ---------------------------------------------------------------------------
// Hot-path eval: u = xc - 1 (common center, no per-interval knot fetch),
// 3-level FSEL binary search -> conflict-free 8-entry LDS.128 -> Horner.
// ---------------------------------------------------------------------------
__device__ __forceinline__ float eval_spline(float xv,
                                             float r1, float r2, float r3, float r4,
                                             float r5, float r6, float r7,
                                             const float4* __restrict__ coef)
{
    float xc = fminf(xv, HI_CLIP);            // inputs >= 0
    float u  = xc - 1.0f;                     // common center; parallel to tree
    bool  b2 = xc >= r4;
    float p1 = b2 ? r6 : r2;
    float q1 = b2 ? r5 : r1;                  // depends only on b2
    float q2 = b2 ? r7 : r3;
    bool  b1 = xc >= p1;
    float p0 = b1 ? q2 : q1;
    bool  b0 = xc >= p0;
    int idx = (b2 ? 4 : 0) + (b1 ? 2 : 0) + (b0 ? 1 : 0);
    float4 cf = coef[idx];                    // 8 x 16B = 128B: conflict-free
    return fmaf(fmaf(fmaf(cf.w, u, cf.z), u, cf.y), u, cf.x);
}

// ---------------------------------------------------------------------------
// Single fused persistent kernel. Prologue per CTA (float-only, keeps regs
// low): stage weights -> tiny MLP -> softmax/cumsum knots -> symbolic de Boor
// -> float Taylor shift to common center x=1 -> shared coef table.
// Main loop: streaming float4, 2 per thread per iteration.
// ---------------------------------------------------------------------------
__global__ __launch_bounds__(256) void fused_spline_kernel(
        const float* __restrict__ x, float* __restrict__ y, int n,
        const float* __restrict__ a,
        const float* __restrict__ W1, const float* __restrict__ b1,
        const float* __restrict__ W2, const float* __restrict__ b2,
        const float* __restrict__ Ww, const float* __restrict__ bw,
        const float* __restrict__ Wk, const float* __restrict__ bk)
{
    __shared__ float sA[1], sW1[16], sB1[16], sW2[256], sB2[16];
    __shared__ float sWW[144], sBW[9], sWK[112], sBK[7];
    __shared__ float n1[16], n2[16], w9[9], kl7[7];
    __shared__ float t[14], c[10], knx[8];
    __shared__ float4 s_coef[8];          // conflict-free LDS.128 table

    int tid = threadIdx.x;

    // ---- stage all 577 weight scalars (one parallel load round) ----
    if (tid == 0) sA[0] = a[0];
    if (tid < 16) { sW1[tid] = W1[tid]; sB1[tid] = b1[tid]; sB2[tid] = b2[tid]; }
    sW2[tid] = W2[tid];
    if (tid < 144) sWW[tid] = Ww[tid];
    if (tid < 112) sWK[tid] = Wk[tid];
    if (tid >= 128 && tid < 137) sBW[tid - 128] = bw[tid - 128];
    if (tid >= 160 && tid < 167) sBK[tid - 160] = bk[tid - 160];
    __syncthreads();

    // ---- layer 1 ----
    if (tid < 16) n1[tid] = sinf(sA[0] * sW1[tid] + sB1[tid]);
    __syncthreads();

    // ---- layer 2 ----
    if (tid < 16) {
        float s = sB2[tid];
        #pragma unroll
        for (int j = 0; j < 16; j++) s += n1[j] * sW2[j * 16 + tid];
        n2[tid] = sinf(s);
    }
    __syncthreads();

    // ---- heads (two warps in parallel) ----
    if (tid < 9) {
        float s = sBW[tid];
        #pragma unroll
        for (int j = 0; j < 16; j++) s += n2[j] * sWW[j * 9 + tid];
        w9[tid] = s;
    }
    if (tid >= 32 && tid < 39) {
        int m = tid - 32;
        float s = sBK[m];
        #pragma unroll
        for (int j = 0; j < 16; j++) s += n2[j] * sWK[j * 7 + m];
        kl7[m] = s;
    }
    __syncthreads();

    // ---- softmax + cumsum -> knots; padded knot vector & control points ----
    if (tid == 0) {
        float mx = kl7[0];
        #pragma unroll
        for (int m = 1; m < 7; m++) mx = fmaxf(mx, kl7[m]);
        float e[7], ssum = 0.f;
        #pragma unroll
        for (int m = 0; m < 7; m++) { e[m] = expf(kl7[m] - mx); ssum += e[m]; }
        float inv = 1.f / ssum;
        float kk[8]; kk[0] = 0.f;
        float cum = 0.f;
        #pragma unroll
        for (int m = 0; m < 7; m++) { cum += e[m] * inv; kk[m + 1] = cum; }

        t[0] = t[1] = t[2] = 0.f;
        #pragma unroll
        for (int m = 0; m < 8; m++) { t[3 + m] = kk[m]; knx[m] = kk[m] * SQ3; }
        t[11] = t[12] = t[13] = 1.f;
        c[0] = 0.f;
        #pragma unroll
        for (int m = 0; m < 9; m++) c[1 + m] = w9[m];
    }
    __syncthreads();

    // ---- symbolic de Boor per interval (threads 0..7, knot index k = 3..10) ----
    if (tid < 8) {
        int k = tid + 3;
        float tkn = t[k];
        float d[4][4];   // d[j][m]: coefficient of u^m (normalized space)
        #pragma unroll
        for (int j = 0; j < 4; j++) {
            int ci = k + j - 3; if (ci > 9) ci = 9;   // JAX clip-mode gather
            d[j][0] = c[ci]; d[j][1] = d[j][2] = d[j][3] = 0.f;
        }
        #pragma unroll
        for (int r = 1; r <= 3; r++) {
            #pragma unroll
            for (int j = 3; j >= 1; j--) {
                if (j < r) continue;
                float lo = t[k + j - 3];
                float hi = t[k + j + 1 - r];
                float dt = hi - lo;
                float invd = (dt > 0.f) ? (1.f / dt) : 0.f;   // guard empty tail interval
                float a0 = (tkn - lo) * invd;                 // alpha(u) = a0 + invd*u
                float em1 = 0.f;
                float nd[4];
                #pragma unroll
                for (int m = 0; m < 4; m++) {
                    float ee = d[j][m] - d[j - 1][m];
                    nd[m] = d[j - 1][m] + a0 * ee + invd * em1;
                    em1 = ee;
                }
                #pragma unroll
                for (int m = 0; m < 4; m++) d[j][m] = nd[m];
            }
        }
        // x-space coeffs about the interval knot, then FLOAT Taylor shift to
        // the common center x = 1 (keeps register count low).
        float a0 = d[3][0];
        float a1 = d[3][1] * IS3;
        float a2 = d[3][2] * (IS3 * IS3);
        float a3 = d[3][3] * (IS3 * IS3 * IS3);
        float s  = fmaf(-tkn, SQ3, 1.0f);          // center - left_knot_x
        float b3f = a3;
        float b2f = fmaf(3.0f * a3, s, a2);
        float b1f = fmaf(fmaf(3.0f * a3, s, 2.0f * a2), s, a1);
        float b0f = fmaf(fmaf(fmaf(a3, s, a2), s, a1), s, a0);
        s_coef[tid] = make_float4(b0f, b1f, b2f, b3f);
    }
    __syncthreads();

    // interior knots (x-space) in registers for the binary search
    const float r1 = knx[1], r2 = knx[2], r3 = knx[3], r4 = knx[4];
    const float r5 = knx[5], r6 = knx[6], r7 = knx[7];

    // ---- main streaming loop: 2 float4 per thread per iteration ----
    int n4 = n >> 2;
    const float4* __restrict__ xin  = (const float4*)x;
    float4* __restrict__       yout = (float4*)y;
    int step = gridDim.x * 512;

    for (int base = blockIdx.x * 512 + tid; base < n4; base += step) {
        int i1 = base + 256;
        bool p1 = i1 < n4;
        float4 v0 = xin[base];            // default caching: L2-resident across replays
        float4 v1;
        if (p1) v1 = xin[i1];

        float4 o0;
        o0.x = eval_spline(v0.x, r1,r2,r3,r4,r5,r6,r7, s_coef);
        o0.y = eval_spline(v0.y, r1,r2,r3,r4,r5,r6,r7, s_coef);
        o0.z = eval_spline(v0.z, r1,r2,r3,r4,r5,r6,r7, s_coef);
        o0.w = eval_spline(v0.w, r1,r2,r3,r4,r5,r6,r7, s_coef);
        __stcs(yout + base, o0);          // streaming store: don't thrash L2

        if (p1) {
            float4 o1;
            o1.x = eval_spline(v1.x, r1,r2,r3,r4,r5,r6,r7, s_coef);
            o1.y = eval_spline(v1.y, r1,r2,r3,r4,r5,r6,r7, s_coef);
            o1.z = eval_spline(v1.z, r1,r2,r3,r4,r5,r6,r7, s_coef);
            o1.w = eval_spline(v1.w, r1,r2,r3,r4,r5,r6,r7, s_coef);
            __stcs(yout + i1, o1);
        }
    }

    // ---- scalar tail (n % 4), handled by block 0 ----
    int rem = n - (n4 << 2);
    if (rem > 0 && blockIdx.x == 0 && tid < rem) {
        int i = (n4 << 2) + tid;
        y[i] = eval_spline(x[i], r1,r2,r3,r4,r5,r6,r7, s_coef);
    }
}

extern "C" void kernel_launch(void* const* d_in, const int* in_sizes, int n_in,
                              void* d_out, int out_size)
{
    const float* x  = (const float*)d_in[0];
    const float* a  = (const float*)d_in[1];
    const float* W1 = (const float*)d_in[2];
    const float* b1 = (const float*)d_in[3];
    const float* W2 = (const float*)d_in[4];
    const float* b2 = (const float*)d_in[5];
    const float* Ww = (const float*)d_in[6];
    const float* bw = (const float*)d_in[7];
    const float* Wk = (const float*)d_in[8];
    const float* bk = (const float*)d_in[9];
    float* out = (float*)d_out;

    int n  = out_size;
    int n4 = n >> 2;
    int blocks = 148 * 8;                      // persistent, ~1 wave
    int needed = (n4 + 511) / 512;
    if (needed < 1) needed = 1;
    if (blocks > needed) blocks = needed;

    fused_spline_kernel<<<blocks, 256>>>(x, out, n,
                                         a, W1, b1, W2, b2, Ww, bw, Wk, bk);
}